// round 6
// baseline (speedup 1.0000x reference)
#include <cuda_runtime.h>
#include <cuda_fp16.h>
#include <cstdint>

#define NEXP 16
#define TTOT 8192
#define DM   1024
#define DF   2048
#define TPE  TTOT
#define BKC  32

#define AH   40                       // smem row stride in halves (conflict-free)
#define A_BYTES   (128*AH*2)          // 10240
#define A_HALVES  (128*AH)
#define BGU_BYTES (128*AH*2)          // 10240 per B matrix (BN=128)
#define STG_GU_B  (A_BYTES + 2*BGU_BYTES)   // 30720
#define SMEM_GU   (2*STG_GU_B)              // 61440
#define BDN_BYTES (256*AH*2)          // 20480 (BN=256)
#define STG_DN_B  (A_BYTES + BDN_BYTES)     // 30720
#define SMEM_DN   (2*STG_DN_B)              // 61440

// ---------------- device scratch ----------------
__device__ int    g_cnt[NEXP];
__device__ int    g_off[NEXP];
__device__ int    g_tok[NEXP*TPE];
__device__ float  g_wt [NEXP*TPE];
__device__ __half g_X16 [(size_t)TTOT*DM];
__device__ __half g_A16 [(size_t)3*TTOT*DF];        // act: dense [0,T), routed [T,3T)
__device__ __half g_WsgT[(size_t)DF*DM];            // [n][k] fp16
__device__ __half g_WsuT[(size_t)DF*DM];
__device__ __half g_WsdT[(size_t)DM*DF];
__device__ __half g_WegT[(size_t)NEXP*DF*DM];
__device__ __half g_WeuT[(size_t)NEXP*DF*DM];
__device__ __half g_WedT[(size_t)NEXP*DM*DF];

// ---------------- helpers ----------------
__device__ __forceinline__ void cp_async16(uint32_t saddr, const void* g, int sz){
    asm volatile("cp.async.ca.shared.global [%0], [%1], 16, %2;\n" :: "r"(saddr), "l"(g), "r"(sz) : "memory");
}
__device__ __forceinline__ void cp_commit(){ asm volatile("cp.async.commit_group;\n" ::: "memory"); }
__device__ __forceinline__ void cp_wait1(){ asm volatile("cp.async.wait_group 1;\n" ::: "memory"); }
__device__ __forceinline__ void cp_wait0(){ asm volatile("cp.async.wait_group 0;\n" ::: "memory"); }
__device__ __forceinline__ uint32_t smem_u32(const void* p){
    uint32_t a;
    asm("{ .reg .u64 t; cvta.to.shared.u64 t, %1; cvt.u32.u64 %0, t; }" : "=r"(a) : "l"(p));
    return a;
}
__device__ __forceinline__ void mma_f16(float c[4], uint32_t a0, uint32_t a1, uint32_t a2, uint32_t a3,
                                        uint32_t b0, uint32_t b1){
    asm volatile("mma.sync.aligned.m16n8k16.row.col.f32.f16.f16.f32 "
                 "{%0,%1,%2,%3}, {%4,%5,%6,%7}, {%8,%9}, {%0,%1,%2,%3};"
                 : "+f"(c[0]), "+f"(c[1]), "+f"(c[2]), "+f"(c[3])
                 : "r"(a0), "r"(a1), "r"(a2), "r"(a3), "r"(b0), "r"(b1));
}
__device__ __forceinline__ uint32_t ldsm32(const __half* p){
    return *reinterpret_cast<const uint32_t*>(p);
}

// ---------------- small kernels ----------------
__global__ void zero_cnt_kernel(){ if (threadIdx.x < NEXP) g_cnt[threadIdx.x] = 0; }

__global__ void scan_kernel(){
    if (threadIdx.x == 0){
        int s = 0;
        #pragma unroll
        for (int e = 0; e < NEXP; e++){ g_off[e] = s; s += g_cnt[e]; }
    }
}

__global__ void x16_kernel(const float* __restrict__ x){
    int i = blockIdx.x*blockDim.x + threadIdx.x;
    float4 v = reinterpret_cast<const float4*>(x)[i];
    __half2 h0 = __floats2half2_rn(v.x, v.y);
    __half2 h1 = __floats2half2_rn(v.z, v.w);
    uint2 o;
    o.x = *reinterpret_cast<uint32_t*>(&h0);
    o.y = *reinterpret_cast<uint32_t*>(&h1);
    reinterpret_cast<uint2*>(g_X16)[i] = o;
}

// transpose + fp16 convert: out[z][c][r] = half(in[z][r][c]); out selected device-side
__global__ void tconv_kernel(const float* __restrict__ in, int R, int C, int which){
    __shared__ float t[32][33];
    __half* out;
    switch (which){
        case 0: out = g_WsgT; break;
        case 1: out = g_WsuT; break;
        case 2: out = g_WsdT; break;
        case 3: out = g_WegT; break;
        case 4: out = g_WeuT; break;
        default: out = g_WedT; break;
    }
    const float* src = in + (size_t)blockIdx.z * R * C;
    __half*      dst = out + (size_t)blockIdx.z * R * C;
    int c0 = blockIdx.x*32, r0 = blockIdx.y*32;
    int tx = threadIdx.x, ty = threadIdx.y;
    #pragma unroll
    for (int j = 0; j < 32; j += 8)
        t[ty+j][tx] = src[(size_t)(r0+ty+j)*C + c0+tx];
    __syncthreads();
    #pragma unroll
    for (int j = 0; j < 32; j += 8)
        dst[(size_t)(c0+ty+j)*R + r0+tx] = __float2half_rn(t[tx][ty+j]);
}

__global__ void router_kernel(const float* __restrict__ x, const float* __restrict__ Wr){
    int gw   = (blockIdx.x*blockDim.x + threadIdx.x) >> 5;
    int lane = threadIdx.x & 31;
    if (gw >= TTOT) return;
    const float* xr = x + (size_t)gw * DM;
    float acc[NEXP];
    #pragma unroll
    for (int e = 0; e < NEXP; e++) acc[e] = 0.f;
    for (int d = lane; d < DM; d += 32){
        float xv = xr[d];
        const float4* wr = reinterpret_cast<const float4*>(Wr + d*NEXP);
        #pragma unroll
        for (int q = 0; q < 4; q++){
            float4 w = wr[q];
            acc[4*q+0] = fmaf(xv, w.x, acc[4*q+0]);
            acc[4*q+1] = fmaf(xv, w.y, acc[4*q+1]);
            acc[4*q+2] = fmaf(xv, w.z, acc[4*q+2]);
            acc[4*q+3] = fmaf(xv, w.w, acc[4*q+3]);
        }
    }
    #pragma unroll
    for (int e = 0; e < NEXP; e++){
        #pragma unroll
        for (int o = 16; o > 0; o >>= 1) acc[e] += __shfl_xor_sync(0xffffffffu, acc[e], o);
    }
    if (lane == 0){
        float mx = acc[0];
        #pragma unroll
        for (int e = 1; e < NEXP; e++) mx = fmaxf(mx, acc[e]);
        float p[NEXP];
        #pragma unroll
        for (int e = 0; e < NEXP; e++) p[e] = __expf(acc[e] - mx);
        float b1 = -1.f, b2 = -1.f; int i1 = 0, i2 = 0;
        #pragma unroll
        for (int e = 0; e < NEXP; e++){
            float v = p[e];
            if (v > b1){ b2 = b1; i2 = i1; b1 = v; i1 = e; }
            else if (v > b2){ b2 = v; i2 = e; }
        }
        float inv = 1.f / (b1 + b2);
        int p1 = atomicAdd(&g_cnt[i1], 1);
        g_tok[i1*TPE + p1] = gw;  g_wt[i1*TPE + p1] = b1 * inv;
        int p2 = atomicAdd(&g_cnt[i2], 1);
        g_tok[i2*TPE + p2] = gw;  g_wt[i2*TPE + p2] = b2 * inv;
    }
}

// ---------------- fused gate+up fp16 GEMM ----------------
// z=0 dense shared expert; z=1..16 routed expert e=z-1 (gathered rows)
__global__ void __launch_bounds__(256)
gu_kernel()
{
    constexpr int KT = DM / BKC;   // 32
    extern __shared__ __half smh[];
    const uint32_t smb = smem_u32(smh);

    const int z = blockIdx.z;
    const bool routed = (z > 0);
    const int e = z - 1;
    const int M = routed ? g_cnt[e] : TTOT;
    const int m0 = blockIdx.y * 128;
    if (m0 >= M) return;
    const int n0 = blockIdx.x * 128;

    const __half* Bg = routed ? g_WegT + (size_t)e*DF*DM : g_WsgT;   // [n][k]
    const __half* Bu = routed ? g_WeuT + (size_t)e*DF*DM : g_WsuT;
    const int abase = routed ? (TTOT + g_off[e]) : 0;

    const int tid = threadIdx.x;
    // loaders: row lr = tid>>1 (0..127), halves offset lc = (tid&1)*16
    const int lr = tid >> 1;
    const int lc = (tid & 1) * 16;
    const __half* arow; int asz;
    {
        int gm = m0 + lr;
        if (routed){
            int ok = gm < M;
            arow = g_X16 + (size_t)(ok ? g_tok[e*TPE + gm] : 0) * DM;
            asz  = ok ? 16 : 0;
        } else { arow = g_X16 + (size_t)gm * DM; asz = 16; }
    }
    const __half* bgrow = Bg + (size_t)(n0 + lr) * DM;
    const __half* burow = Bu + (size_t)(n0 + lr) * DM;

    auto load_chunk = [&](int kt, int s){
        const int k0 = kt * BKC;
        const uint32_t sb = smb + s*STG_GU_B;
        const uint32_t da = sb + lr*(AH*2) + lc*2;
        cp_async16(da,      arow + k0 + lc,     asz);
        cp_async16(da + 16, arow + k0 + lc + 8, asz);
        const uint32_t dg = sb + A_BYTES + lr*(AH*2) + lc*2;
        cp_async16(dg,      bgrow + k0 + lc,     16);
        cp_async16(dg + 16, bgrow + k0 + lc + 8, 16);
        const uint32_t du = dg + BGU_BYTES;
        cp_async16(du,      burow + k0 + lc,     16);
        cp_async16(du + 16, burow + k0 + lc + 8, 16);
    };

    const int wid = tid >> 5, lane = tid & 31;
    const int g = lane >> 2, t = lane & 3;
    const int wm = wid & 1;     // 2 x 64 rows
    const int wn = wid >> 1;    // 4 x 32 cols

    float cg[4][4][4], cu[4][4][4];
    #pragma unroll
    for (int i = 0; i < 4; i++)
        #pragma unroll
        for (int j = 0; j < 4; j++)
            #pragma unroll
            for (int q = 0; q < 4; q++){ cg[i][j][q] = 0.f; cu[i][j][q] = 0.f; }

    load_chunk(0, 0); cp_commit();

    for (int kt = 0; kt < KT; kt++){
        const int s = kt & 1;
        if (kt + 1 < KT){ load_chunk(kt+1, s^1); cp_commit(); cp_wait1(); }
        else            { cp_wait0(); }
        __syncthreads();

        const __half* As0 = smh + (size_t)s*(STG_GU_B/2);
        const __half* ab  = As0 + (wm*64 + g)*AH + 2*t;
        const __half* bgb = As0 + A_HALVES + (wn*32 + g)*AH + 2*t;
        const __half* bub = bgb + A_HALVES;   // Bu right after Bg (same size)

        #pragma unroll
        for (int kk = 0; kk < BKC; kk += 16){
            uint32_t a[4][4], bg[4][2], bu[4][2];
            #pragma unroll
            for (int i = 0; i < 4; i++){
                const __half* ar = ab + i*16*AH + kk;
                a[i][0] = ldsm32(ar);
                a[i][1] = ldsm32(ar + 8*AH);
                a[i][2] = ldsm32(ar + 8);
                a[i][3] = ldsm32(ar + 8*AH + 8);
            }
            #pragma unroll
            for (int j = 0; j < 4; j++){
                const __half* br = bgb + j*8*AH + kk;
                bg[j][0] = ldsm32(br);
                bg[j][1] = ldsm32(br + 8);
                const __half* br2 = bub + j*8*AH + kk;
                bu[j][0] = ldsm32(br2);
                bu[j][1] = ldsm32(br2 + 8);
            }
            #pragma unroll
            for (int i = 0; i < 4; i++)
                #pragma unroll
                for (int j = 0; j < 4; j++){
                    mma_f16(cg[i][j], a[i][0], a[i][1], a[i][2], a[i][3], bg[j][0], bg[j][1]);
                    mma_f16(cu[i][j], a[i][0], a[i][1], a[i][2], a[i][3], bu[j][0], bu[j][1]);
                }
        }
        __syncthreads();
    }

    // epilogue: ACT = half( silu(G) * U )
    #pragma unroll
    for (int i = 0; i < 4; i++){
        #pragma unroll
        for (int h = 0; h < 2; h++){
            const int gm = m0 + wm*64 + i*16 + g + h*8;
            if (routed && gm >= M) continue;
            __half* drow = g_A16 + (size_t)(abase + gm)*DF;
            #pragma unroll
            for (int j = 0; j < 4; j++){
                const int cc = n0 + wn*32 + j*8 + 2*t;
                float g0 = cg[i][j][2*h], g1 = cg[i][j][2*h+1];
                float u0 = cu[i][j][2*h], u1 = cu[i][j][2*h+1];
                float o0 = u0 * (g0 / (1.f + __expf(-g0)));
                float o1 = u1 * (g1 / (1.f + __expf(-g1)));
                *reinterpret_cast<__half2*>(drow + cc) = __floats2half2_rn(o0, o1);
            }
        }
    }
}

// ---------------- down fp16 GEMM (BN=256, warp tile 64x64) ----------------
template<int ROUTED>
__global__ void __launch_bounds__(256)
down_kernel(float* __restrict__ Out)
{
    constexpr int KT = DF / BKC;   // 64
    extern __shared__ __half smh[];
    const uint32_t smb = smem_u32(smh);

    const int e  = ROUTED ? blockIdx.z : 0;
    const int M  = ROUTED ? g_cnt[e] : TTOT;
    const int m0 = blockIdx.y * 128;
    if (m0 >= M) return;
    const int n0 = blockIdx.x * 256;

    const __half* B = ROUTED ? g_WedT + (size_t)e*DM*DF : g_WsdT;    // [n=DM][k=DF]
    const int offe = ROUTED ? g_off[e] : 0;
    const __half* A = g_A16 + (size_t)(ROUTED ? (TTOT + offe) : 0) * DF;

    const int tid = threadIdx.x;
    const int lr = tid >> 1;
    const int lc = (tid & 1) * 16;
    const __half* arow; int asz;
    {
        int gm = m0 + lr;
        int ok = (!ROUTED) || (gm < M);
        arow = A + (size_t)(ok ? gm : 0) * DF;
        asz  = ok ? 16 : 0;
    }
    const __half* brow = B + (size_t)(n0 + tid) * DF;   // one n-row per thread (256 rows)

    auto load_chunk = [&](int kt, int s){
        const int k0 = kt * BKC;
        const uint32_t sb = smb + s*STG_DN_B;
        const uint32_t da = sb + lr*(AH*2) + lc*2;
        cp_async16(da,      arow + k0 + lc,     asz);
        cp_async16(da + 16, arow + k0 + lc + 8, asz);
        const uint32_t db = sb + A_BYTES + tid*(AH*2);
        #pragma unroll
        for (int q = 0; q < 4; q++)
            cp_async16(db + q*16, brow + k0 + q*8, 16);
    };

    const int wid = tid >> 5, lane = tid & 31;
    const int g = lane >> 2, t = lane & 3;
    const int wm = wid & 1;
    const int wn = wid >> 1;   // 4 x 64 cols

    float c[4][8][4];
    #pragma unroll
    for (int i = 0; i < 4; i++)
        #pragma unroll
        for (int j = 0; j < 8; j++)
            #pragma unroll
            for (int q = 0; q < 4; q++) c[i][j][q] = 0.f;

    load_chunk(0, 0); cp_commit();

    for (int kt = 0; kt < KT; kt++){
        const int s = kt & 1;
        if (kt + 1 < KT){ load_chunk(kt+1, s^1); cp_commit(); cp_wait1(); }
        else            { cp_wait0(); }
        __syncthreads();

        const __half* As0 = smh + (size_t)s*(STG_DN_B/2);
        const __half* ab  = As0 + (wm*64 + g)*AH + 2*t;
        const __half* bb  = As0 + A_HALVES + (wn*64 + g)*AH + 2*t;

        #pragma unroll
        for (int kk = 0; kk < BKC; kk += 16){
            uint32_t a[4][4], b[8][2];
            #pragma unroll
            for (int i = 0; i < 4; i++){
                const __half* ar = ab + i*16*AH + kk;
                a[i][0] = ldsm32(ar);
                a[i][1] = ldsm32(ar + 8*AH);
                a[i][2] = ldsm32(ar + 8);
                a[i][3] = ldsm32(ar + 8*AH + 8);
            }
            #pragma unroll
            for (int j = 0; j < 8; j++){
                const __half* br = bb + j*8*AH + kk;
                b[j][0] = ldsm32(br);
                b[j][1] = ldsm32(br + 8);
            }
            #pragma unroll
            for (int i = 0; i < 4; i++)
                #pragma unroll
                for (int j = 0; j < 8; j++)
                    mma_f16(c[i][j], a[i][0], a[i][1], a[i][2], a[i][3], b[j][0], b[j][1]);
        }
        __syncthreads();
    }

    #pragma unroll
    for (int i = 0; i < 4; i++){
        #pragma unroll
        for (int h = 0; h < 2; h++){
            const int gm = m0 + wm*64 + i*16 + g + h*8;
            if (ROUTED && gm >= M) continue;
            int tok = gm; float w = 1.f;
            if (ROUTED){ tok = g_tok[e*TPE + gm]; w = g_wt[e*TPE + gm]; }
            float* orow = Out + (size_t)tok*DM;
            #pragma unroll
            for (int j = 0; j < 8; j++){
                const int cc = n0 + wn*64 + j*8 + 2*t;
                const float v0 = c[i][j][2*h], v1 = c[i][j][2*h+1];
                if (!ROUTED){
                    *reinterpret_cast<float2*>(orow + cc) = make_float2(v0, v1);
                } else {
                    atomicAdd(orow + cc + 0, w * v0);
                    atomicAdd(orow + cc + 1, w * v1);
                }
            }
        }
    }
}

// ---------------- launch ----------------
extern "C" void kernel_launch(void* const* d_in, const int* in_sizes, int n_in,
                              void* d_out, int out_size)
{
    const float* x   = (const float*)d_in[0];
    const float* Wr  = (const float*)d_in[1];
    const float* Wsg = (const float*)d_in[2];
    const float* Wsu = (const float*)d_in[3];
    const float* Wsd = (const float*)d_in[4];
    const float* Weg = (const float*)d_in[5];
    const float* Weu = (const float*)d_in[6];
    const float* Wed = (const float*)d_in[7];
    float* out = (float*)d_out;

    cudaFuncSetAttribute(gu_kernel,      cudaFuncAttributeMaxDynamicSharedMemorySize, SMEM_GU);
    cudaFuncSetAttribute(down_kernel<0>, cudaFuncAttributeMaxDynamicSharedMemorySize, SMEM_DN);
    cudaFuncSetAttribute(down_kernel<1>, cudaFuncAttributeMaxDynamicSharedMemorySize, SMEM_DN);

    zero_cnt_kernel<<<1, 32>>>();
    router_kernel<<<TTOT/8, 256>>>(x, Wr);
    scan_kernel<<<1, 32>>>();
    x16_kernel<<<(TTOT*DM/4)/256, 256>>>(x);

    dim3 tb32(32, 8);
    tconv_kernel<<<dim3(DF/32, DM/32, 1),    tb32>>>(Wsg, DM, DF, 0);
    tconv_kernel<<<dim3(DF/32, DM/32, 1),    tb32>>>(Wsu, DM, DF, 1);
    tconv_kernel<<<dim3(DM/32, DF/32, 1),    tb32>>>(Wsd, DF, DM, 2);
    tconv_kernel<<<dim3(DF/32, DM/32, NEXP), tb32>>>(Weg, DM, DF, 3);
    tconv_kernel<<<dim3(DF/32, DM/32, NEXP), tb32>>>(Weu, DM, DF, 4);
    tconv_kernel<<<dim3(DM/32, DF/32, NEXP), tb32>>>(Wed, DF, DM, 5);

    dim3 blk(256);
    gu_kernel<<<dim3(DF/128, TTOT/128, NEXP+1), blk, SMEM_GU>>>();
    down_kernel<0><<<dim3(DM/256, TTOT/128, 1),   blk, SMEM_DN>>>(out);
    down_kernel<1><<<dim3(DM/256, TPE/128, NEXP), blk, SMEM_DN>>>(out);
}